// round 1
// baseline (speedup 1.0000x reference)
#include <cuda_runtime.h>
#include <cstddef>

// Problem constants (fixed by the reference setup)
#define BATCH 32
#define SEQ   512
#define DIM   1024
#define NCOLS (BATCH * DIM)   // 32768 independent columns
#define T_SUBSTEPS 4

// 1.0f / 0.001f correctly rounded = 999.99994f; for sp in {0,1} multiplying by
// this is bitwise identical to dividing by 0.001f (the reference's spikes/DT).
#define INV_DT (1.0f / 0.001f)

__global__ __launch_bounds__(128, 8)
void dual_threshold_scan_kernel(const float* __restrict__ inputs,
                                const float* __restrict__ init_state,
                                float* __restrict__ out)
{
    const int col = blockIdx.x * blockDim.x + threadIdx.x;   // 0..NCOLS-1
    if (col >= NCOLS) return;

    const int b = col >> 10;          // col / DIM
    const int d = col & (DIM - 1);    // col % DIM

    const size_t base = (size_t)b * SEQ * DIM + d;
    const float* __restrict__ ip = inputs + base;
    float*       __restrict__ op = out + base;

    float v = init_state[col];

    #pragma unroll 8
    for (int s = 0; s < SEQ; ++s) {
        // Load is independent of the v-chain: unroll lets ptxas batch these.
        const float x = __ldcs(ip + (size_t)s * DIM);
        const float r = fmaxf(x, 0.0f) * 0.001f;   // relu(x) * DT, exact vs ref

        float sp = 0.0f;
        #pragma unroll
        for (int i = 0; i < T_SUBSTEPS; ++i) {
            // Reference does: v += r; sp = floor(v); v -= sp;
            // With v in [0,1) and r < 1:  a = v + r  lies in [0, 2), so
            //   floor(a)  == (a >= 1) ? 1 : 0        (exact)
            //   a - floor(a) == (a >= 1) ? a - 1 : a (exact, a-1.0f is the
            //                                         literal ref subtraction)
            const float a  = v + r;
            const float am = a - 1.0f;       // off the compare path
            const bool  hit = (a >= 1.0f);
            sp = hit ? 1.0f : 0.0f;
            v  = hit ? am   : a;
        }

        __stcs(op + (size_t)s * DIM, sp * INV_DT);
    }
}

extern "C" void kernel_launch(void* const* d_in, const int* in_sizes, int n_in,
                              void* d_out, int out_size)
{
    const float* inputs     = (const float*)d_in[0];  // [32, 512, 1024] f32
    const float* init_state = (const float*)d_in[1];  // [32, 1024] f32
    float*       out        = (float*)d_out;          // [32, 512, 1024] f32

    (void)in_sizes; (void)n_in; (void)out_size;

    const int threads = 128;
    const int blocks  = (NCOLS + threads - 1) / threads;  // 256
    dual_threshold_scan_kernel<<<blocks, threads>>>(inputs, init_state, out);
}

// round 2
// speedup vs baseline: 4.6270x; 4.6270x over previous
#include <cuda_runtime.h>
#include <cstddef>

// Problem constants (fixed by the reference setup)
#define BATCH 32
#define SEQ   512
#define DIM   1024
#define NCOLS (BATCH * DIM)   // 32768 independent columns
#define T_SUBSTEPS 4
#define PF 16                 // software-pipeline depth (register ring buffer)

// 1.0f / 0.001f correctly rounded = 999.99994f; for sp in {0,1} multiplying by
// this is bitwise identical to dividing by 0.001f (the reference's spikes/DT).
#define INV_DT (1.0f / 0.001f)

__device__ __forceinline__ float step4(float& v, float r)
{
    // Reference inner loop, bitwise-faithful:
    //   v += r; sp = floor(v); v -= sp;   (x4)
    // With v in [0,1) and 0 <= r < 1:  a = v + r in [0,2), so
    //   floor(a)     == (a >= 1) ? 1.0f : 0.0f
    //   a - floor(a) == (a >= 1) ? a - 1.0f : a      (exact)
    float sp = 0.0f;
    #pragma unroll
    for (int i = 0; i < T_SUBSTEPS; ++i) {
        const float a  = v + r;
        const float am = a - 1.0f;        // off the compare path
        const bool  h  = (a >= 1.0f);
        sp = h ? 1.0f : 0.0f;
        v  = h ? am   : a;
    }
    return sp;
}

__global__ __launch_bounds__(128)
void dual_threshold_scan_kernel(const float* __restrict__ inputs,
                                const float* __restrict__ init_state,
                                float* __restrict__ out)
{
    const int col = blockIdx.x * blockDim.x + threadIdx.x;   // 0..NCOLS-1
    if (col >= NCOLS) return;

    const int b = col >> 10;          // col / DIM
    const int d = col & (DIM - 1);    // col % DIM

    const size_t base = (size_t)b * SEQ * DIM + d;
    const float* __restrict__ ip = inputs + base;
    float*       __restrict__ op = out + base;

    float v = init_state[col];

    // Prologue: fill the 16-deep register pipeline.
    float buf[PF];
    #pragma unroll
    for (int j = 0; j < PF; ++j)
        buf[j] = __ldcs(ip + (size_t)j * DIM);

    // Main loop: consume chunk k while prefetching chunk k+1.
    // Loads are independent of the v-chain, so ~PF loads stay in flight.
    for (int s0 = 0; s0 < SEQ - PF; s0 += PF) {
        #pragma unroll
        for (int j = 0; j < PF; ++j) {
            const float x = buf[j];
            buf[j] = __ldcs(ip + (size_t)(s0 + PF + j) * DIM);  // prefetch
            const float r  = fmaxf(x, 0.0f) * 0.001f;           // relu * DT
            const float sp = step4(v, r);
            __stcs(op + (size_t)(s0 + j) * DIM, sp * INV_DT);
        }
    }

    // Epilogue: last chunk, no prefetch.
    {
        const int s0 = SEQ - PF;
        #pragma unroll
        for (int j = 0; j < PF; ++j) {
            const float x  = buf[j];
            const float r  = fmaxf(x, 0.0f) * 0.001f;
            const float sp = step4(v, r);
            __stcs(op + (size_t)(s0 + j) * DIM, sp * INV_DT);
        }
    }
}

extern "C" void kernel_launch(void* const* d_in, const int* in_sizes, int n_in,
                              void* d_out, int out_size)
{
    const float* inputs     = (const float*)d_in[0];  // [32, 512, 1024] f32
    const float* init_state = (const float*)d_in[1];  // [32, 1024] f32
    float*       out        = (float*)d_out;          // [32, 512, 1024] f32

    (void)in_sizes; (void)n_in; (void)out_size;

    const int threads = 128;
    const int blocks  = (NCOLS + threads - 1) / threads;  // 256
    dual_threshold_scan_kernel<<<blocks, threads>>>(inputs, init_state, out);
}